// round 1
// baseline (speedup 1.0000x reference)
#include <cuda_runtime.h>

// Problem constants
#define T_STEPS 256
#define I1 38
#define H1 50
#define H2 15
#define NC 14
#define K1 (I1 + H1)    // 88  rows of combined layer-1 weight (x then h1)
#define G1 (4 * H1)     // 200 gates layer 1
#define K2 (H1 + H2)    // 65  rows of combined layer-2 weight (h1 then h2)
#define G2 (4 * H2)     // 60  gates layer 2
#define BT 16           // batch rows per block
#define AST 20          // activation row stride (padded, 16B-aligned for b%4==0)
#define NTHREADS 256
#define NBLOCKS 256     // 4096 / BT

// Shared layout (floats):
//  W1s  [K1][G1]              17600
//  W2s  [K2][G2]               3900
//  bias1[G1]                    200
//  bias2[G2]                     60
//  wfcs [NC*H2]                 210
//  bfcs [NC]                     14
//  a1   [2][K1][AST]           3520
//  a2   [2][K2][AST]           2600
#define OFF_W1   0
#define OFF_W2   (OFF_W1 + K1 * G1)
#define OFF_B1   (OFF_W2 + K2 * G2)
#define OFF_B2   (OFF_B1 + G1)
#define OFF_WFC  (OFF_B2 + G2)
#define OFF_BFC  (OFF_WFC + NC * H2)
#define OFF_A1   (OFF_BFC + NC)
#define OFF_A2   (OFF_A1 + 2 * K1 * AST)
#define SMEM_FLOATS (OFF_A2 + 2 * K2 * AST)
#define SMEM_BYTES (SMEM_FLOATS * 4)

__device__ __forceinline__ float fsig(float x) {
    return __fdividef(1.0f, 1.0f + __expf(-x));
}
__device__ __forceinline__ float ftanh_fast(float x) {
    // tanh(x) = 1 - 2/(1 + e^{2x}); robust at +/- inf of exp
    return 1.0f - __fdividef(2.0f, 1.0f + __expf(2.0f * x));
}

extern __shared__ float smem[];

__global__ __launch_bounds__(NTHREADS, 2)
void lstm2_fused_kernel(const float* __restrict__ x,
                        const float* __restrict__ w_ih1, const float* __restrict__ w_hh1,
                        const float* __restrict__ b_ih1, const float* __restrict__ b_hh1,
                        const float* __restrict__ w_ih2, const float* __restrict__ w_hh2,
                        const float* __restrict__ b_ih2, const float* __restrict__ b_hh2,
                        const float* __restrict__ w_fc, const float* __restrict__ b_fc,
                        float* __restrict__ out)
{
    float* W1s   = smem + OFF_W1;
    float* W2s   = smem + OFF_W2;
    float* bias1 = smem + OFF_B1;
    float* bias2 = smem + OFF_B2;
    float* wfcs  = smem + OFF_WFC;
    float* bfcs  = smem + OFF_BFC;
    float* a1    = smem + OFF_A1;   // [2][K1][AST]: rows 0..I1-1 = x_t, rows I1.. = h1
    float* a2    = smem + OFF_A2;   // [2][K2][AST]: rows 0..H1-1 = h1(new), rows H1.. = h2

    const int tid = threadIdx.x;
    const int b0  = blockIdx.x * BT;

    // ---- stage weights into shared (k-major for broadcast-friendly reads) ----
    for (int i = tid; i < G1 * I1; i += NTHREADS) { int g = i / I1, k = i % I1; W1s[k * G1 + g] = w_ih1[i]; }
    for (int i = tid; i < G1 * H1; i += NTHREADS) { int g = i / H1, k = i % H1; W1s[(I1 + k) * G1 + g] = w_hh1[i]; }
    for (int i = tid; i < G2 * H1; i += NTHREADS) { int g = i / H1, k = i % H1; W2s[k * G2 + g] = w_ih2[i]; }
    for (int i = tid; i < G2 * H2; i += NTHREADS) { int g = i / H2, k = i % H2; W2s[(H1 + k) * G2 + g] = w_hh2[i]; }
    for (int i = tid; i < G1; i += NTHREADS) bias1[i] = b_ih1[i] + b_hh1[i];
    for (int i = tid; i < G2; i += NTHREADS) bias2[i] = b_ih2[i] + b_hh2[i];
    for (int i = tid; i < NC * H2; i += NTHREADS) wfcs[i] = w_fc[i];
    for (int i = tid; i < NC; i += NTHREADS) bfcs[i] = b_fc[i];

    // ---- zero initial hidden states in buffer 0; load x_0 into buffer 0 ----
    for (int i = tid; i < H1 * AST; i += NTHREADS) a1[I1 * AST + i] = 0.0f;
    for (int i = tid; i < H2 * AST; i += NTHREADS) a2[H1 * AST + i] = 0.0f;
    for (int i = tid; i < BT * I1; i += NTHREADS) {
        int b = i / I1, k = i % I1;
        a1[k * AST + b] = x[(size_t)(b0 + b) * (T_STEPS * I1) + k];
    }
    __syncthreads();

    // ---- persistent per-thread roles & cell state in registers ----
    const int u  = tid >> 2;     // layer-1 unit, valid for tid < 200
    const int bq = tid & 3;      // batch quad
    float c1r[4] = {0.f, 0.f, 0.f, 0.f};

    const int u2 = tid % 15;     // layer-2 unit, valid for tid < 120
    const int bp = tid / 15;     // batch pair index (0..7)
    float c2r[2] = {0.f, 0.f};

    for (int t = 0; t < T_STEPS; ++t) {
        const int p = t & 1, q = p ^ 1;
        float* a1p = a1 + p * (K1 * AST);
        float* a1q = a1 + q * (K1 * AST);
        float* a2p = a2 + p * (K2 * AST);
        float* a2q = a2 + q * (K2 * AST);

        // ===== Phase 1: layer-1 gates + state update; spare threads prefetch x_{t+1} =====
        if (tid < 200) {
            float accs[4][4];
            #pragma unroll
            for (int gi = 0; gi < 4; ++gi) {
                float bv = bias1[u + gi * H1];
                accs[gi][0] = bv; accs[gi][1] = bv; accs[gi][2] = bv; accs[gi][3] = bv;
            }
            const float* wp = W1s + u;
            const float* ap = a1p + 4 * bq;
            #pragma unroll 4
            for (int k = 0; k < K1; ++k) {
                float4 av = *reinterpret_cast<const float4*>(ap); ap += AST;
                float w0 = wp[0];
                float w1 = wp[H1];
                float w2 = wp[2 * H1];
                float w3 = wp[3 * H1];
                wp += G1;
                accs[0][0] += w0 * av.x; accs[0][1] += w0 * av.y; accs[0][2] += w0 * av.z; accs[0][3] += w0 * av.w;
                accs[1][0] += w1 * av.x; accs[1][1] += w1 * av.y; accs[1][2] += w1 * av.z; accs[1][3] += w1 * av.w;
                accs[2][0] += w2 * av.x; accs[2][1] += w2 * av.y; accs[2][2] += w2 * av.z; accs[2][3] += w2 * av.w;
                accs[3][0] += w3 * av.x; accs[3][1] += w3 * av.y; accs[3][2] += w3 * av.z; accs[3][3] += w3 * av.w;
            }
            #pragma unroll
            for (int bj = 0; bj < 4; ++bj) {
                float ig = fsig(accs[0][bj]);
                float fg = fsig(accs[1][bj]);
                float gg = ftanh_fast(accs[2][bj]);
                float og = fsig(accs[3][bj]);
                float c  = fg * c1r[bj] + ig * gg;
                c1r[bj]  = c;
                float h  = og * ftanh_fast(c);
                int b = 4 * bq + bj;
                a1q[(I1 + u) * AST + b] = h;   // next step's layer-1 h input
                a2q[u * AST + b]        = h;   // this step's layer-2 input
            }
        } else {
            // threads 200..255: prefetch x_{t+1} into buffer q under the compute shadow
            if (t + 1 < T_STEPS) {
                for (int i = tid - 200; i < BT * I1; i += (NTHREADS - 200)) {
                    int b = i / I1, k = i % I1;
                    a1q[k * AST + b] = x[(size_t)(b0 + b) * (T_STEPS * I1) + (size_t)(t + 1) * I1 + k];
                }
            }
        }

        __syncthreads();   // the ONLY barrier per step (hazards analyzed: safe)

        // ===== Phase 2: layer-2 (reads new h1 from buf q, old h2 from buf p) =====
        // Overlaps with next iteration's phase 1 of other threads — no conflict.
        if (tid < 120) {
            float acB[4][2];
            #pragma unroll
            for (int gi = 0; gi < 4; ++gi) {
                float bv = bias2[u2 + gi * H2];
                acB[gi][0] = bv; acB[gi][1] = bv;
            }
            const float* wp2 = W2s + u2;
            const float* ap2 = a2q + 2 * bp;          // h1 (new)
            #pragma unroll 5
            for (int k = 0; k < H1; ++k) {
                float2 av = *reinterpret_cast<const float2*>(ap2); ap2 += AST;
                float w0 = wp2[0];
                float w1 = wp2[H2];
                float w2 = wp2[2 * H2];
                float w3 = wp2[3 * H2];
                wp2 += G2;
                acB[0][0] += w0 * av.x; acB[0][1] += w0 * av.y;
                acB[1][0] += w1 * av.x; acB[1][1] += w1 * av.y;
                acB[2][0] += w2 * av.x; acB[2][1] += w2 * av.y;
                acB[3][0] += w3 * av.x; acB[3][1] += w3 * av.y;
            }
            const float* ap2b = a2p + H1 * AST + 2 * bp;  // h2 (old)
            #pragma unroll
            for (int k = 0; k < H2; ++k) {
                float2 av = *reinterpret_cast<const float2*>(ap2b); ap2b += AST;
                float w0 = wp2[0];
                float w1 = wp2[H2];
                float w2 = wp2[2 * H2];
                float w3 = wp2[3 * H2];
                wp2 += G2;
                acB[0][0] += w0 * av.x; acB[0][1] += w0 * av.y;
                acB[1][0] += w1 * av.x; acB[1][1] += w1 * av.y;
                acB[2][0] += w2 * av.x; acB[2][1] += w2 * av.y;
                acB[3][0] += w3 * av.x; acB[3][1] += w3 * av.y;
            }
            #pragma unroll
            for (int bj = 0; bj < 2; ++bj) {
                float ig = fsig(acB[0][bj]);
                float fg = fsig(acB[1][bj]);
                float gg = ftanh_fast(acB[2][bj]);
                float og = fsig(acB[3][bj]);
                float c  = fg * c2r[bj] + ig * gg;
                c2r[bj]  = c;
                float h  = og * ftanh_fast(c);
                a2q[(H1 + u2) * AST + 2 * bp + bj] = h;
            }
        }
        // no barrier here: next-iteration phase 1 touches disjoint buffers/rows
    }

    __syncthreads();
    // final h2 lives in buffer q of the last step: q = ((T-1)&1)^1 = 0
    const int qf = ((T_STEPS - 1) & 1) ^ 1;
    if (tid < BT * NC) {
        int b = tid / NC, n = tid % NC;
        const float* h2f = a2 + qf * (K2 * AST) + H1 * AST;
        float s = bfcs[n];
        #pragma unroll
        for (int j = 0; j < H2; ++j)
            s += h2f[j * AST + b] * wfcs[n * H2 + j];
        out[(size_t)(b0 + b) * NC + n] = s;
    }
}

extern "C" void kernel_launch(void* const* d_in, const int* in_sizes, int n_in,
                              void* d_out, int out_size)
{
    (void)in_sizes; (void)n_in; (void)out_size;
    const float* x     = (const float*)d_in[0];
    const float* w_ih1 = (const float*)d_in[1];
    const float* w_hh1 = (const float*)d_in[2];
    const float* b_ih1 = (const float*)d_in[3];
    const float* b_hh1 = (const float*)d_in[4];
    const float* w_ih2 = (const float*)d_in[5];
    const float* w_hh2 = (const float*)d_in[6];
    const float* b_ih2 = (const float*)d_in[7];
    const float* b_hh2 = (const float*)d_in[8];
    const float* w_fc  = (const float*)d_in[9];
    const float* b_fc  = (const float*)d_in[10];
    float* out = (float*)d_out;

    cudaFuncSetAttribute(lstm2_fused_kernel,
                         cudaFuncAttributeMaxDynamicSharedMemorySize, SMEM_BYTES);

    lstm2_fused_kernel<<<NBLOCKS, NTHREADS, SMEM_BYTES>>>(
        x, w_ih1, w_hh1, b_ih1, b_hh1,
        w_ih2, w_hh2, b_ih2, b_hh2,
        w_fc, b_fc, out);
}

// round 2
// speedup vs baseline: 1.1521x; 1.1521x over previous
#include <cuda_runtime.h>

// Problem constants
#define T_STEPS 256
#define I1 38
#define H1 50
#define H2 15
#define NC 14
#define K1 (I1 + H1)    // 88
#define G1 (4 * H1)     // 200
#define K2 (H1 + H2)    // 65
#define G2 (4 * H2)     // 60
#define BT 16
#define AST 20          // activation row stride (floats); 80B rows, 16B aligned
#define NTHREADS 256
#define NBLOCKS 256

// Shared layout (floats):
//  W1s  [K1][H1][4]   17600   (k, unit, gate) -> float4 per (k,u)
//  W2s  [K2][H2][4]    3900
//  b1v  [H1][4]         200
//  b2v  [H2][4]          60
//  wfcs [NC*H2]         210
//  bfcs [NC]             14
//  a1   [2][K1][AST]   3520
//  a2   [2][K2][AST]   2600
#define OFF_W1   0
#define OFF_W2   (OFF_W1 + K1 * H1 * 4)
#define OFF_B1   (OFF_W2 + K2 * H2 * 4)
#define OFF_B2   (OFF_B1 + H1 * 4)
#define OFF_WFC  (OFF_B2 + H2 * 4)
#define OFF_BFC  (OFF_WFC + NC * H2)
#define OFF_A1   (OFF_BFC + NC)
#define OFF_A2   (OFF_A1 + 2 * K1 * AST)
#define SMEM_FLOATS (OFF_A2 + 2 * K2 * AST)
#define SMEM_BYTES (SMEM_FLOATS * 4)

__device__ __forceinline__ float fsig(float x) {
    return __fdividef(1.0f, 1.0f + __expf(-x));
}
__device__ __forceinline__ float ftanh_fast(float x) {
    return 1.0f - __fdividef(2.0f, 1.0f + __expf(2.0f * x));
}

// ---- packed f32x2 helpers (sm_100+) ----
__device__ __forceinline__ unsigned long long pack2(float w) {
    unsigned long long r;
    asm("mov.b64 %0, {%1, %1};" : "=l"(r) : "f"(w));
    return r;
}
__device__ __forceinline__ void ffma2(unsigned long long& d,
                                      unsigned long long a, unsigned long long b) {
    asm("fma.rn.f32x2 %0, %1, %2, %0;" : "+l"(d) : "l"(a), "l"(b));
}
__device__ __forceinline__ float2 unpk2(unsigned long long v) {
    float2 r;
    asm("mov.b64 {%0, %1}, %2;" : "=f"(r.x), "=f"(r.y) : "l"(v));
    return r;
}

extern __shared__ float smem[];

__global__ __launch_bounds__(NTHREADS, 2)
void lstm2_fused_kernel(const float* __restrict__ x,
                        const float* __restrict__ w_ih1, const float* __restrict__ w_hh1,
                        const float* __restrict__ b_ih1, const float* __restrict__ b_hh1,
                        const float* __restrict__ w_ih2, const float* __restrict__ w_hh2,
                        const float* __restrict__ b_ih2, const float* __restrict__ b_hh2,
                        const float* __restrict__ w_fc, const float* __restrict__ b_fc,
                        float* __restrict__ out)
{
    float* W1s   = smem + OFF_W1;
    float* W2s   = smem + OFF_W2;
    float* b1v   = smem + OFF_B1;
    float* b2v   = smem + OFF_B2;
    float* wfcs  = smem + OFF_WFC;
    float* bfcs  = smem + OFF_BFC;
    float* a1    = smem + OFF_A1;
    float* a2    = smem + OFF_A2;

    const int tid = threadIdx.x;
    const int b0  = blockIdx.x * BT;

    // ---- stage weights, repacked as (k, unit, gate) float4 groups ----
    for (int i = tid; i < K1 * H1 * 4; i += NTHREADS) {
        int k = i / (H1 * 4);
        int r = i - k * (H1 * 4);
        int uu = r >> 2, gi = r & 3;
        float v = (k < I1) ? w_ih1[(gi * H1 + uu) * I1 + k]
                           : w_hh1[(gi * H1 + uu) * H1 + (k - I1)];
        W1s[i] = v;
    }
    for (int i = tid; i < K2 * H2 * 4; i += NTHREADS) {
        int k = i / (H2 * 4);
        int r = i - k * (H2 * 4);
        int uu = r >> 2, gi = r & 3;
        float v = (k < H1) ? w_ih2[(gi * H2 + uu) * H1 + k]
                           : w_hh2[(gi * H2 + uu) * H2 + (k - H1)];
        W2s[i] = v;
    }
    for (int i = tid; i < H1 * 4; i += NTHREADS) {
        int uu = i >> 2, gi = i & 3;
        b1v[i] = b_ih1[gi * H1 + uu] + b_hh1[gi * H1 + uu];
    }
    for (int i = tid; i < H2 * 4; i += NTHREADS) {
        int uu = i >> 2, gi = i & 3;
        b2v[i] = b_ih2[gi * H2 + uu] + b_hh2[gi * H2 + uu];
    }
    for (int i = tid; i < NC * H2; i += NTHREADS) wfcs[i] = w_fc[i];
    for (int i = tid; i < NC; i += NTHREADS) bfcs[i] = b_fc[i];

    // ---- zero initial states in buffer 0; load x_0 ----
    for (int i = tid; i < H1 * AST; i += NTHREADS) a1[I1 * AST + i] = 0.0f;
    for (int i = tid; i < H2 * AST; i += NTHREADS) a2[H1 * AST + i] = 0.0f;
    for (int i = tid; i < BT * I1; i += NTHREADS) {
        int b = i / I1, k = i % I1;
        a1[k * AST + b] = x[(size_t)(b0 + b) * (T_STEPS * I1) + k];
    }
    __syncthreads();

    const int u  = tid >> 2;     // layer-1 unit (tid < 200)
    const int bq = tid & 3;      // batch quad
    float c1r[4] = {0.f, 0.f, 0.f, 0.f};

    const int u2 = tid % 15;     // layer-2 unit (tid < 120)
    const int bp = tid / 15;     // batch pair (0..7)
    float c2r[2] = {0.f, 0.f};

    for (int t = 0; t < T_STEPS; ++t) {
        const int p = t & 1, q = p ^ 1;
        float* a1p = a1 + p * (K1 * AST);
        float* a1q = a1 + q * (K1 * AST);
        float* a2p = a2 + p * (K2 * AST);
        float* a2q = a2 + q * (K2 * AST);

        // ===== Phase 1: layer-1 gates; spare threads prefetch x_{t+1} =====
        if (tid < 200) {
            unsigned long long acc[4][2];
            #pragma unroll
            for (int gi = 0; gi < 4; ++gi) {
                unsigned long long bv = pack2(b1v[u * 4 + gi]);
                acc[gi][0] = bv; acc[gi][1] = bv;
            }
            const float4* wp = reinterpret_cast<const float4*>(W1s) + u;
            const float* ap = a1p + 4 * bq;
            #pragma unroll 4
            for (int k = 0; k < K1; ++k) {
                float4 wv = wp[0]; wp += H1;
                ulonglong2 av = *reinterpret_cast<const ulonglong2*>(ap); ap += AST;
                unsigned long long w0 = pack2(wv.x);
                unsigned long long w1 = pack2(wv.y);
                unsigned long long w2 = pack2(wv.z);
                unsigned long long w3 = pack2(wv.w);
                ffma2(acc[0][0], w0, av.x); ffma2(acc[0][1], w0, av.y);
                ffma2(acc[1][0], w1, av.x); ffma2(acc[1][1], w1, av.y);
                ffma2(acc[2][0], w2, av.x); ffma2(acc[2][1], w2, av.y);
                ffma2(acc[3][0], w3, av.x); ffma2(acc[3][1], w3, av.y);
            }
            #pragma unroll
            for (int h = 0; h < 2; ++h) {
                float2 iv = unpk2(acc[0][h]);
                float2 fv = unpk2(acc[1][h]);
                float2 gv = unpk2(acc[2][h]);
                float2 ov = unpk2(acc[3][h]);
                #pragma unroll
                for (int l = 0; l < 2; ++l) {
                    int bj = 2 * h + l;
                    float ig = fsig(l ? iv.y : iv.x);
                    float fg = fsig(l ? fv.y : fv.x);
                    float gg = ftanh_fast(l ? gv.y : gv.x);
                    float og = fsig(l ? ov.y : ov.x);
                    float c  = fg * c1r[bj] + ig * gg;
                    c1r[bj]  = c;
                    float hh = og * ftanh_fast(c);
                    int b = 4 * bq + bj;
                    a1q[(I1 + u) * AST + b] = hh;
                    a2q[u * AST + b]        = hh;
                }
            }
        } else {
            if (t + 1 < T_STEPS) {
                for (int i = tid - 200; i < BT * I1; i += (NTHREADS - 200)) {
                    int b = i / I1, k = i % I1;
                    a1q[k * AST + b] =
                        x[(size_t)(b0 + b) * (T_STEPS * I1) + (size_t)(t + 1) * I1 + k];
                }
            }
        }

        __syncthreads();   // the ONLY barrier per step

        // ===== Phase 2: layer-2 (reads new h1 in buf q, old h2 in buf p) =====
        if (tid < 120) {
            unsigned long long acc[4];
            #pragma unroll
            for (int gi = 0; gi < 4; ++gi) acc[gi] = pack2(b2v[u2 * 4 + gi]);

            const float4* wp2 = reinterpret_cast<const float4*>(W2s) + u2;
            const float* ap2 = a2q + 2 * bp;          // h1 (new)
            #pragma unroll 5
            for (int k = 0; k < H1; ++k) {
                float4 wv = wp2[0]; wp2 += H2;
                unsigned long long av = *reinterpret_cast<const unsigned long long*>(ap2);
                ap2 += AST;
                ffma2(acc[0], pack2(wv.x), av);
                ffma2(acc[1], pack2(wv.y), av);
                ffma2(acc[2], pack2(wv.z), av);
                ffma2(acc[3], pack2(wv.w), av);
            }
            const float* ap2b = a2p + H1 * AST + 2 * bp;  // h2 (old)
            #pragma unroll
            for (int k = 0; k < H2; ++k) {
                float4 wv = wp2[0]; wp2 += H2;
                unsigned long long av = *reinterpret_cast<const unsigned long long*>(ap2b);
                ap2b += AST;
                ffma2(acc[0], pack2(wv.x), av);
                ffma2(acc[1], pack2(wv.y), av);
                ffma2(acc[2], pack2(wv.z), av);
                ffma2(acc[3], pack2(wv.w), av);
            }
            float2 iv = unpk2(acc[0]);
            float2 fv = unpk2(acc[1]);
            float2 gv = unpk2(acc[2]);
            float2 ov = unpk2(acc[3]);
            #pragma unroll
            for (int l = 0; l < 2; ++l) {
                float ig = fsig(l ? iv.y : iv.x);
                float fg = fsig(l ? fv.y : fv.x);
                float gg = ftanh_fast(l ? gv.y : gv.x);
                float og = fsig(l ? ov.y : ov.x);
                float c  = fg * c2r[l] + ig * gg;
                c2r[l]   = c;
                float hh = og * ftanh_fast(c);
                a2q[(H1 + u2) * AST + 2 * bp + l] = hh;
            }
        }
        // no barrier: next phase-1 touches disjoint rows/buffers
    }

    __syncthreads();
    const int qf = ((T_STEPS - 1) & 1) ^ 1;
    if (tid < BT * NC) {
        int b = tid / NC, n = tid % NC;
        const float* h2f = a2 + qf * (K2 * AST) + H1 * AST;
        float s = bfcs[n];
        #pragma unroll
        for (int j = 0; j < H2; ++j)
            s += h2f[j * AST + b] * wfcs[n * H2 + j];
        out[(size_t)(b0 + b) * NC + n] = s;
    }
}

extern "C" void kernel_launch(void* const* d_in, const int* in_sizes, int n_in,
                              void* d_out, int out_size)
{
    (void)in_sizes; (void)n_in; (void)out_size;
    const float* x     = (const float*)d_in[0];
    const float* w_ih1 = (const float*)d_in[1];
    const float* w_hh1 = (const float*)d_in[2];
    const float* b_ih1 = (const float*)d_in[3];
    const float* b_hh1 = (const float*)d_in[4];
    const float* w_ih2 = (const float*)d_in[5];
    const float* w_hh2 = (const float*)d_in[6];
    const float* b_ih2 = (const float*)d_in[7];
    const float* b_hh2 = (const float*)d_in[8];
    const float* w_fc  = (const float*)d_in[9];
    const float* b_fc  = (const float*)d_in[10];
    float* out = (float*)d_out;

    cudaFuncSetAttribute(lstm2_fused_kernel,
                         cudaFuncAttributeMaxDynamicSharedMemorySize, SMEM_BYTES);

    lstm2_fused_kernel<<<NBLOCKS, NTHREADS, SMEM_BYTES>>>(
        x, w_ih1, w_hh1, b_ih1, b_hh1,
        w_ih2, w_hh2, b_ih2, b_hh2,
        w_fc, b_fc, out);
}